// round 5
// baseline (speedup 1.0000x reference)
#include <cuda_runtime.h>
#include <cuda_bf16.h>
#include <mma.h>
#include <cstdint>

using namespace nvcuda;

// ---------------- problem constants ----------------
constexpr int Bv   = 64;
constexpr int Hv   = 56;
constexpr int Wv   = 56;
constexpr int Cv   = 192;
constexpr int HEADS= 6;
constexpr int WS   = 7;
constexpr int SS   = 3;
constexpr int MLPD = 768;
constexpr int NT   = 49;              // tokens per window
constexpr int HD   = 32;              // head dim
constexpr int Lv   = Hv * Wv;         // 3136
constexpr int MT   = Bv * Lv;         // 200704 rows
constexpr float SCALE = 0.17677669529663687f; // 32^-0.5

// ---------------- device scratch ----------------
__device__ __nv_bfloat16 g_hwin[(size_t)MT * Cv];
__device__ __nv_bfloat16 g_Q[(size_t)MT * Cv];
__device__ __nv_bfloat16 g_K[(size_t)MT * Cv];
__device__ __nv_bfloat16 g_V[(size_t)MT * Cv];
__device__ __nv_bfloat16 g_attn[(size_t)MT * Cv];
__device__ float         g_x1[(size_t)MT * Cv];
__device__ __nv_bfloat16 g_h2n[(size_t)MT * Cv];
__device__ __nv_bfloat16 g_mid[(size_t)MT * MLPD];
__device__ __nv_bfloat16 g_wqkv[Cv * 3 * Cv];
__device__ __nv_bfloat16 g_wproj[Cv * Cv];
__device__ __nv_bfloat16 g_w1[Cv * MLPD];
__device__ __nv_bfloat16 g_w2[MLPD * Cv];
__device__ float         g_bm[64 * HEADS * NT * NT];   // bias+mask table (batch-invariant)

// ---------------- cp.async helpers ----------------
__device__ __forceinline__ void cp16(void* d, const void* s) {
    unsigned sa = (unsigned)__cvta_generic_to_shared(d);
    asm volatile("cp.async.cg.shared.global [%0], [%1], 16;" :: "r"(sa), "l"(s));
}
#define CP_COMMIT() asm volatile("cp.async.commit_group;")
#define CP_WAIT2()  asm volatile("cp.async.wait_group 2;")

// ---------------- weight conversion fp32 -> bf16 ----------------
__global__ void cvt_weights(const float* __restrict__ qkvw,
                            const float* __restrict__ projw,
                            const float* __restrict__ w1,
                            const float* __restrict__ w2) {
    constexpr int n0 = Cv * 3 * Cv;
    constexpr int n1 = Cv * Cv;
    constexpr int n2 = Cv * MLPD;
    constexpr int n3 = MLPD * Cv;
    constexpr int tot = n0 + n1 + n2 + n3;
    for (int i = blockIdx.x * blockDim.x + threadIdx.x; i < tot;
         i += gridDim.x * blockDim.x) {
        if (i < n0)                  g_wqkv[i]             = __float2bfloat16(qkvw[i]);
        else if (i < n0 + n1)        g_wproj[i - n0]       = __float2bfloat16(projw[i - n0]);
        else if (i < n0 + n1 + n2)   g_w1[i - n0 - n1]     = __float2bfloat16(w1[i - n0 - n1]);
        else                         g_w2[i - n0 - n1 - n2]= __float2bfloat16(w2[i - n0 - n1 - n2]);
    }
}

// ---------------- shift-mask region helper + bias table ----------------
__device__ __forceinline__ int reg3(int r) { return r < 49 ? 0 : (r < 53 ? 1 : 2); }

__global__ void bm_kernel(const float* __restrict__ rpb) {
    int e = blockIdx.x * blockDim.x + threadIdx.x;
    constexpr int TOT = 64 * HEADS * NT * NT;
    if (e >= TOT) return;
    int j   = e % NT;
    int i   = (e / NT) % NT;
    int h   = (e / (NT * NT)) % HEADS;
    int wi  = e / (NT * NT * HEADS);
    int wh = wi >> 3, ww = wi & 7;
    int ih = i / WS, iw = i - ih * WS;
    int jh = j / WS, jw = j - jh * WS;
    int idx = (ih - jh + WS - 1) * (2 * WS - 1) + (iw - jw + WS - 1);
    float v = rpb[idx * HEADS + h];
    int li = reg3(wh * WS + ih) * 3 + reg3(ww * WS + iw);
    int lj = reg3(wh * WS + jh) * 3 + reg3(ww * WS + jw);
    if (li != lj) v -= 100.f;
    g_bm[e] = v;
}

// ---------------- LayerNorm kernels (one warp per row) ----------------
__global__ void ln1_kernel(const float* __restrict__ x,
                           const float* __restrict__ g,
                           const float* __restrict__ b) {
    int warp = threadIdx.x >> 5, lane = threadIdx.x & 31;
    int m = blockIdx.x * 8 + warp;
    int win = m / NT, tok = m - win * NT;
    int bi  = win >> 6, wi = win & 63;
    int wh  = wi >> 3, ww = wi & 7;
    int ih  = tok / WS, iw = tok - ih * WS;
    int r   = (wh * WS + ih + SS) % Hv;
    int c   = (ww * WS + iw + SS) % Wv;
    const float* row = x + ((size_t)bi * Lv + r * Wv + c) * Cv;
    float v[6];
#pragma unroll
    for (int k = 0; k < 6; k++) v[k] = row[lane + 32 * k];
    float s = 0.f;
#pragma unroll
    for (int k = 0; k < 6; k++) s += v[k];
#pragma unroll
    for (int o = 16; o; o >>= 1) s += __shfl_xor_sync(0xffffffffu, s, o);
    float mean = s * (1.f / 192.f);
    float q = 0.f;
#pragma unroll
    for (int k = 0; k < 6; k++) { float d = v[k] - mean; q += d * d; }
#pragma unroll
    for (int o = 16; o; o >>= 1) q += __shfl_xor_sync(0xffffffffu, q, o);
    float rstd = rsqrtf(q * (1.f / 192.f) + 1e-5f);
#pragma unroll
    for (int k = 0; k < 6; k++) {
        int cc = lane + 32 * k;
        g_hwin[(size_t)m * Cv + cc] = __float2bfloat16((v[k] - mean) * rstd * g[cc] + b[cc]);
    }
}

__global__ void ln2_kernel(const float* __restrict__ g,
                           const float* __restrict__ b) {
    int warp = threadIdx.x >> 5, lane = threadIdx.x & 31;
    int m = blockIdx.x * 8 + warp;
    const float* row = g_x1 + (size_t)m * Cv;
    float v[6];
#pragma unroll
    for (int k = 0; k < 6; k++) v[k] = row[lane + 32 * k];
    float s = 0.f;
#pragma unroll
    for (int k = 0; k < 6; k++) s += v[k];
#pragma unroll
    for (int o = 16; o; o >>= 1) s += __shfl_xor_sync(0xffffffffu, s, o);
    float mean = s * (1.f / 192.f);
    float q = 0.f;
#pragma unroll
    for (int k = 0; k < 6; k++) { float d = v[k] - mean; q += d * d; }
#pragma unroll
    for (int o = 16; o; o >>= 1) q += __shfl_xor_sync(0xffffffffu, q, o);
    float rstd = rsqrtf(q * (1.f / 192.f) + 1e-5f);
#pragma unroll
    for (int k = 0; k < 6; k++) {
        int cc = lane + 32 * k;
        g_h2n[(size_t)m * Cv + cc] = __float2bfloat16((v[k] - mean) * rstd * g[cc] + b[cc]);
    }
}

// ---------------- tensor-core attention: one block per window ----------------
__global__ __launch_bounds__(256) void attn_wmma() {
    int win = blockIdx.x;              // 0..4095
    int wi  = win & 63;
    int tid = threadIdx.x, warp = tid >> 5, lane = tid & 31;

    __shared__ __align__(16) __nv_bfloat16 Qs[64 * 40];
    __shared__ __align__(16) __nv_bfloat16 Ks[64 * 40];
    __shared__ __align__(16) __nv_bfloat16 Vs[64 * 40];
    __shared__ __align__(16) float         Ss[64 * 68];   // aliased as Os [64*36]
    __shared__ __align__(16) __nv_bfloat16 Ps[64 * 72];
    float* Os = Ss;

    for (int head = 0; head < HEADS; head++) {
        size_t base = (size_t)(win * HEADS + head) * NT * HD;
        for (int id = tid; id < 196; id += 256) {
            int r = id >> 2, c8 = (id & 3) * 8;
            *(uint4*)&Qs[r * 40 + c8] = *(const uint4*)&g_Q[base + id * 8];
            *(uint4*)&Ks[r * 40 + c8] = *(const uint4*)&g_K[base + id * 8];
            *(uint4*)&Vs[r * 40 + c8] = *(const uint4*)&g_V[base + id * 8];
        }
        for (int id = tid; id < 60; id += 256) {       // rows 49..63 of V = 0
            int r = 49 + (id >> 2), c8 = (id & 3) * 8;
            *(uint4*)&Vs[r * 40 + c8] = make_uint4(0, 0, 0, 0);
        }
        __syncthreads();

        // S = Q @ K^T (64x64x32)
        {
            int mrow = (warp >> 1) * 16, ncol = (warp & 1) * 32;
            wmma::fragment<wmma::accumulator, 16, 16, 16, float> acc[2];
            wmma::fill_fragment(acc[0], 0.f);
            wmma::fill_fragment(acc[1], 0.f);
#pragma unroll
            for (int kk = 0; kk < 32; kk += 16) {
                wmma::fragment<wmma::matrix_a, 16, 16, 16, __nv_bfloat16, wmma::row_major> af;
                wmma::load_matrix_sync(af, &Qs[mrow * 40 + kk], 40);
#pragma unroll
                for (int j = 0; j < 2; j++) {
                    wmma::fragment<wmma::matrix_b, 16, 16, 16, __nv_bfloat16, wmma::col_major> bf;
                    wmma::load_matrix_sync(bf, &Ks[(ncol + j * 16) * 40 + kk], 40);
                    wmma::mma_sync(acc[j], af, bf, acc[j]);
                }
            }
#pragma unroll
            for (int j = 0; j < 2; j++)
                wmma::store_matrix_sync(&Ss[mrow * 68 + ncol + j * 16], acc[j], 68,
                                        wmma::mem_row_major);
        }
        __syncthreads();

        // softmax rows 0..48 with precomputed bias+mask
        {
            const float* bmp = g_bm + (size_t)(wi * HEADS + head) * (NT * NT);
            for (int row = warp; row < NT; row += 8) {
                int j1 = lane + 32;
                float s0 = Ss[row * 68 + lane] + bmp[row * NT + lane];
                float s1 = (j1 < NT) ? Ss[row * 68 + j1] + bmp[row * NT + j1] : -1e30f;
                float mx = fmaxf(s0, s1);
#pragma unroll
                for (int o = 16; o; o >>= 1) mx = fmaxf(mx, __shfl_xor_sync(0xffffffffu, mx, o));
                float e0 = __expf(s0 - mx);
                float e1 = (j1 < NT) ? __expf(s1 - mx) : 0.f;
                float sm = e0 + e1;
#pragma unroll
                for (int o = 16; o; o >>= 1) sm += __shfl_xor_sync(0xffffffffu, sm, o);
                float inv = 1.f / sm;
                Ps[row * 72 + lane] = __float2bfloat16(e0 * inv);
                Ps[row * 72 + j1]   = __float2bfloat16(e1 * inv);
            }
        }
        __syncthreads();

        // O = P @ V (64x32x64)
        {
            int mrow = (warp >> 1) * 16, ncol = (warp & 1) * 16;
            wmma::fragment<wmma::accumulator, 16, 16, 16, float> acc;
            wmma::fill_fragment(acc, 0.f);
#pragma unroll
            for (int kk = 0; kk < 64; kk += 16) {
                wmma::fragment<wmma::matrix_a, 16, 16, 16, __nv_bfloat16, wmma::row_major> af;
                wmma::fragment<wmma::matrix_b, 16, 16, 16, __nv_bfloat16, wmma::row_major> bf;
                wmma::load_matrix_sync(af, &Ps[mrow * 72 + kk], 72);
                wmma::load_matrix_sync(bf, &Vs[kk * 40 + ncol], 40);
                wmma::mma_sync(acc, af, bf, acc);
            }
            wmma::store_matrix_sync(&Os[mrow * 36 + ncol], acc, 36, wmma::mem_row_major);
        }
        __syncthreads();

        // write O rows < 49 (vectorized: thread -> (row, 16-col half))
        if (tid < 98) {
            int r = tid >> 1, d0 = (tid & 1) * 16;
            __nv_bfloat16* dst = &g_attn[((size_t)win * NT + r) * Cv + head * HD + d0];
            const float* src = &Os[r * 36 + d0];
#pragma unroll
            for (int cc = 0; cc < 16; cc += 8) {
                float4 a = *(const float4*)&src[cc];
                float4 b = *(const float4*)&src[cc + 4];
                __nv_bfloat16 o[8] = {
                    __float2bfloat16(a.x), __float2bfloat16(a.y),
                    __float2bfloat16(a.z), __float2bfloat16(a.w),
                    __float2bfloat16(b.x), __float2bfloat16(b.y),
                    __float2bfloat16(b.z), __float2bfloat16(b.w)};
                *(uint4*)&dst[cc] = *(const uint4*)o;
            }
        }
        __syncthreads();
    }
}

// ---------------- pipelined bf16 wmma GEMM (cp.async, 3 stages, BK=32) --------
template <int EPI>
__global__ __launch_bounds__(256) void gemm_k(const float* __restrict__ bias,
                                              const float* __restrict__ xin,
                                              float* __restrict__ outf) {
    constexpr int K = (EPI == 3) ? MLPD : Cv;
    constexpr int N = (EPI == 0) ? 3 * Cv : (EPI == 2) ? MLPD : Cv;
    constexpr int BK = 32;
    constexpr int NK = K / BK;

    const __nv_bfloat16* __restrict__ A =
        (EPI == 0) ? g_hwin : (EPI == 1) ? g_attn : (EPI == 2) ? g_h2n : g_mid;
    const __nv_bfloat16* __restrict__ Bm =
        (EPI == 0) ? g_wqkv : (EPI == 1) ? g_wproj : (EPI == 2) ? g_w1 : g_w2;

    __shared__ __align__(16) unsigned char smbuf[3 * 128 * 40 * 2 + 3 * 32 * 72 * 2];
    __nv_bfloat16* As = (__nv_bfloat16*)smbuf;
    __nv_bfloat16* Bs = (__nv_bfloat16*)(smbuf + 3 * 128 * 40 * 2);
    float*         Cs = (float*)smbuf;

    const int tid = threadIdx.x;
    const int m0 = blockIdx.y * 128;
    const int n0 = blockIdx.x * 64;
    const int warp = tid >> 5, wm = warp >> 1, wn = warp & 1;

    auto load_stage = [&](int kt, int stg) {
        int k0 = kt * BK;
        __nv_bfloat16* as = As + stg * (128 * 40);
        __nv_bfloat16* bs = Bs + stg * (32 * 72);
#pragma unroll
        for (int i = 0; i < 2; i++) {
            int id = tid + i * 256;
            int r = id >> 2, c8 = (id & 3) * 8;
            cp16(&as[r * 40 + c8], &A[(size_t)(m0 + r) * K + k0 + c8]);
        }
        {
            int r = tid >> 3, c8 = (tid & 7) * 8;
            cp16(&bs[r * 72 + c8], &Bm[(size_t)(k0 + r) * N + n0 + c8]);
        }
    };

    wmma::fragment<wmma::accumulator, 16, 16, 16, float> acc[2][2];
#pragma unroll
    for (int i = 0; i < 2; i++)
#pragma unroll
        for (int j = 0; j < 2; j++) wmma::fill_fragment(acc[i][j], 0.f);

    load_stage(0, 0); CP_COMMIT();
    load_stage(1, 1); CP_COMMIT();

    for (int kt = 0; kt < NK; kt++) {
        if (kt + 2 < NK) load_stage(kt + 2, (kt + 2) % 3);
        CP_COMMIT();
        CP_WAIT2();
        __syncthreads();
        const __nv_bfloat16* as = As + (kt % 3) * (128 * 40);
        const __nv_bfloat16* bs = Bs + (kt % 3) * (32 * 72);
#pragma unroll
        for (int kk = 0; kk < BK; kk += 16) {
            wmma::fragment<wmma::matrix_a, 16, 16, 16, __nv_bfloat16, wmma::row_major> af[2];
            wmma::fragment<wmma::matrix_b, 16, 16, 16, __nv_bfloat16, wmma::row_major> bfr[2];
            wmma::load_matrix_sync(af[0], &as[(wm * 32 + 0)  * 40 + kk], 40);
            wmma::load_matrix_sync(af[1], &as[(wm * 32 + 16) * 40 + kk], 40);
            wmma::load_matrix_sync(bfr[0], &bs[kk * 72 + wn * 32 + 0],  72);
            wmma::load_matrix_sync(bfr[1], &bs[kk * 72 + wn * 32 + 16], 72);
#pragma unroll
            for (int i = 0; i < 2; i++)
#pragma unroll
                for (int j = 0; j < 2; j++)
                    wmma::mma_sync(acc[i][j], af[i], bfr[j], acc[i][j]);
        }
        __syncthreads();
    }

#pragma unroll
    for (int i = 0; i < 2; i++)
#pragma unroll
        for (int j = 0; j < 2; j++)
            wmma::store_matrix_sync(&Cs[(wm * 32 + i * 16) * 68 + wn * 32 + j * 16],
                                    acc[i][j], 68, wmma::mem_row_major);
    __syncthreads();

    // -------- strength-reduced vectorized epilogue: thread -> (row, 32-col half)
    {
        const int r = tid >> 1, cbase = (tid & 1) * 32;
        const int m = m0 + r;
        const float* crow = &Cs[r * 68 + cbase];
        const int nb = n0 + cbase;

        if constexpr (EPI == 0) {
            int sel  = nb / Cv;
            int head = (nb - sel * Cv) >> 5;
            int win = m / NT, tok = m - win * NT;
            __nv_bfloat16* dst =
                (sel == 0 ? g_Q : sel == 1 ? g_K : g_V) +
                ((size_t)(win * HEADS + head) * NT + tok) * HD;
            const float sc = (sel == 0) ? SCALE : 1.f;
#pragma unroll
            for (int cc = 0; cc < 32; cc += 8) {
                float4 a = *(const float4*)&crow[cc];
                float4 b = *(const float4*)&crow[cc + 4];
                float4 ba = *(const float4*)&bias[nb + cc];
                float4 bb = *(const float4*)&bias[nb + cc + 4];
                __nv_bfloat16 o[8] = {
                    __float2bfloat16((a.x + ba.x) * sc), __float2bfloat16((a.y + ba.y) * sc),
                    __float2bfloat16((a.z + ba.z) * sc), __float2bfloat16((a.w + ba.w) * sc),
                    __float2bfloat16((b.x + bb.x) * sc), __float2bfloat16((b.y + bb.y) * sc),
                    __float2bfloat16((b.z + bb.z) * sc), __float2bfloat16((b.w + bb.w) * sc)};
                *(uint4*)&dst[cc] = *(const uint4*)o;
            }
        } else if constexpr (EPI == 1) {
            int win = m / NT, tok = m - win * NT;
            int bi = win >> 6, wi = win & 63;
            int wh = wi >> 3, ww = wi & 7;
            int ih = tok / WS, iw = tok - ih * WS;
            int r2 = (wh * WS + ih + SS) % Hv;
            int c2 = (ww * WS + iw + SS) % Wv;
            size_t pos = ((size_t)bi * Lv + r2 * Wv + c2) * Cv + nb;
#pragma unroll
            for (int cc = 0; cc < 32; cc += 4) {
                float4 v  = *(const float4*)&crow[cc];
                float4 bv = *(const float4*)&bias[nb + cc];
                float4 xv = *(const float4*)&xin[pos + cc];
                float4 o = make_float4(v.x + bv.x + xv.x, v.y + bv.y + xv.y,
                                       v.z + bv.z + xv.z, v.w + bv.w + xv.w);
                *(float4*)&g_x1[pos + cc] = o;
            }
        } else if constexpr (EPI == 2) {
            size_t pos = (size_t)m * MLPD + nb;
#pragma unroll
            for (int cc = 0; cc < 32; cc += 8) {
                float4 a = *(const float4*)&crow[cc];
                float4 b = *(const float4*)&crow[cc + 4];
                float4 ba = *(const float4*)&bias[nb + cc];
                float4 bb = *(const float4*)&bias[nb + cc + 4];
                float vv[8] = {a.x + ba.x, a.y + ba.y, a.z + ba.z, a.w + ba.w,
                               b.x + bb.x, b.y + bb.y, b.z + bb.z, b.w + bb.w};
                __nv_bfloat16 o[8];
#pragma unroll
                for (int u = 0; u < 8; u++) {
                    float t = vv[u];
                    o[u] = __float2bfloat16(
                        0.5f * t * (1.f + erff(t * 0.70710678118654752f)));
                }
                *(uint4*)&g_mid[pos + cc] = *(const uint4*)o;
            }
        } else {
            size_t pos = (size_t)m * Cv + nb;
#pragma unroll
            for (int cc = 0; cc < 32; cc += 4) {
                float4 v  = *(const float4*)&crow[cc];
                float4 bv = *(const float4*)&bias[nb + cc];
                float4 xv = *(const float4*)&g_x1[pos + cc];
                float4 o = make_float4(v.x + bv.x + xv.x, v.y + bv.y + xv.y,
                                       v.z + bv.z + xv.z, v.w + bv.w + xv.w);
                *(float4*)&outf[pos + cc] = o;
            }
        }
    }
}

// ---------------- launch ----------------
extern "C" void kernel_launch(void* const* d_in, const int* in_sizes, int n_in,
                              void* d_out, int out_size) {
    const float* x      = (const float*)d_in[0];
    const float* ln1_g  = (const float*)d_in[1];
    const float* ln1_b  = (const float*)d_in[2];
    const float* qkv_w  = (const float*)d_in[3];
    const float* qkv_b  = (const float*)d_in[4];
    const float* proj_w = (const float*)d_in[5];
    const float* proj_b = (const float*)d_in[6];
    const float* rpb    = (const float*)d_in[7];
    const float* ln2_g  = (const float*)d_in[8];
    const float* ln2_b  = (const float*)d_in[9];
    const float* mlp_w1 = (const float*)d_in[10];
    const float* mlp_b1 = (const float*)d_in[11];
    const float* mlp_w2 = (const float*)d_in[12];
    const float* mlp_b2 = (const float*)d_in[13];
    float* out = (float*)d_out;

    cvt_weights<<<432, 1024>>>(qkv_w, proj_w, mlp_w1, mlp_w2);
    bm_kernel<<<(64 * HEADS * NT * NT + 255) / 256, 256>>>(rpb);
    ln1_kernel<<<MT / 8, 256>>>(x, ln1_g, ln1_b);
    gemm_k<0><<<dim3(3 * Cv / 64, MT / 128), 256>>>(qkv_b, nullptr, nullptr);
    attn_wmma<<<Bv * 64, 256>>>();
    gemm_k<1><<<dim3(Cv / 64, MT / 128), 256>>>(proj_b, x, nullptr);
    ln2_kernel<<<MT / 8, 256>>>(ln2_g, ln2_b);
    gemm_k<2><<<dim3(MLPD / 64, MT / 128), 256>>>(mlp_b1, nullptr, nullptr);
    gemm_k<3><<<dim3(Cv / 64, MT / 128), 256>>>(mlp_b2, nullptr, out);
}

// round 8
// speedup vs baseline: 1.2203x; 1.2203x over previous
#include <cuda_runtime.h>
#include <cuda_bf16.h>
#include <mma.h>
#include <cstdint>

using namespace nvcuda;

// ---------------- problem constants ----------------
constexpr int Bv   = 64;
constexpr int Hv   = 56;
constexpr int Wv   = 56;
constexpr int Cv   = 192;
constexpr int HEADS= 6;
constexpr int WS   = 7;
constexpr int SS   = 3;
constexpr int MLPD = 768;
constexpr int NT   = 49;              // tokens per window
constexpr int HD   = 32;              // head dim
constexpr int Lv   = Hv * Wv;         // 3136
constexpr int MT   = Bv * Lv;         // 200704 rows
constexpr float SCALE = 0.17677669529663687f; // 32^-0.5

// ---------------- device scratch ----------------
__device__ __nv_bfloat16 g_hwin[(size_t)MT * Cv];
__device__ __nv_bfloat16 g_Q[(size_t)MT * Cv];
__device__ __nv_bfloat16 g_K[(size_t)MT * Cv];
__device__ __nv_bfloat16 g_V[(size_t)MT * Cv];
__device__ __nv_bfloat16 g_attn[(size_t)MT * Cv];
__device__ float         g_x1[(size_t)MT * Cv];
__device__ __nv_bfloat16 g_h2n[(size_t)MT * Cv];
__device__ __nv_bfloat16 g_mid[(size_t)MT * MLPD];
__device__ __nv_bfloat16 g_wqkv[Cv * 3 * Cv];
__device__ __nv_bfloat16 g_wproj[Cv * Cv];
__device__ __nv_bfloat16 g_w1[Cv * MLPD];
__device__ __nv_bfloat16 g_w2[MLPD * Cv];
__device__ float         g_bm[64 * HEADS * NT * NT];   // bias+mask table

// ---------------- cp.async helpers ----------------
__device__ __forceinline__ void cp16(void* d, const void* s) {
    unsigned sa = (unsigned)__cvta_generic_to_shared(d);
    asm volatile("cp.async.cg.shared.global [%0], [%1], 16;" :: "r"(sa), "l"(s));
}
#define CP_COMMIT() asm volatile("cp.async.commit_group;")
#define CP_WAIT1()  asm volatile("cp.async.wait_group 1;")

// smem bytes for gemm tile width NTL (stages vs fp32 C-staging, whichever larger)
constexpr size_t gemm_smem(int NTL) {
    size_t stages = 3ull * (128 * 40 + 32 * (NTL + 8)) * 2;
    size_t cs     = 128ull * (NTL + 4) * 4;
    return stages > cs ? stages : cs;
}

// ---------------- weight conversion fp32 -> bf16 ----------------
__global__ void cvt_weights(const float* __restrict__ qkvw,
                            const float* __restrict__ projw,
                            const float* __restrict__ w1,
                            const float* __restrict__ w2) {
    constexpr int n0 = Cv * 3 * Cv;
    constexpr int n1 = Cv * Cv;
    constexpr int n2 = Cv * MLPD;
    constexpr int n3 = MLPD * Cv;
    constexpr int tot = n0 + n1 + n2 + n3;
    for (int i = blockIdx.x * blockDim.x + threadIdx.x; i < tot;
         i += gridDim.x * blockDim.x) {
        if (i < n0)                  g_wqkv[i]             = __float2bfloat16(qkvw[i]);
        else if (i < n0 + n1)        g_wproj[i - n0]       = __float2bfloat16(projw[i - n0]);
        else if (i < n0 + n1 + n2)   g_w1[i - n0 - n1]     = __float2bfloat16(w1[i - n0 - n1]);
        else                         g_w2[i - n0 - n1 - n2]= __float2bfloat16(w2[i - n0 - n1 - n2]);
    }
}

// ---------------- shift-mask region helper + bias table ----------------
__device__ __forceinline__ int reg3(int r) { return r < 49 ? 0 : (r < 53 ? 1 : 2); }

__global__ void bm_kernel(const float* __restrict__ rpb) {
    int e = blockIdx.x * blockDim.x + threadIdx.x;
    constexpr int TOT = 64 * HEADS * NT * NT;
    if (e >= TOT) return;
    int j   = e % NT;
    int i   = (e / NT) % NT;
    int h   = (e / (NT * NT)) % HEADS;
    int wi  = e / (NT * NT * HEADS);
    int wh = wi >> 3, ww = wi & 7;
    int ih = i / WS, iw = i - ih * WS;
    int jh = j / WS, jw = j - jh * WS;
    int idx = (ih - jh + WS - 1) * (2 * WS - 1) + (iw - jw + WS - 1);
    float v = rpb[idx * HEADS + h];
    int li = reg3(wh * WS + ih) * 3 + reg3(ww * WS + iw);
    int lj = reg3(wh * WS + jh) * 3 + reg3(ww * WS + jw);
    if (li != lj) v -= 100.f;
    g_bm[e] = v;
}

// ---------------- LayerNorm kernels (one warp per row) ----------------
__global__ void ln1_kernel(const float* __restrict__ x,
                           const float* __restrict__ g,
                           const float* __restrict__ b) {
    int warp = threadIdx.x >> 5, lane = threadIdx.x & 31;
    int m = blockIdx.x * 8 + warp;
    int win = m / NT, tok = m - win * NT;
    int bi  = win >> 6, wi = win & 63;
    int wh  = wi >> 3, ww = wi & 7;
    int ih  = tok / WS, iw = tok - ih * WS;
    int r   = (wh * WS + ih + SS) % Hv;
    int c   = (ww * WS + iw + SS) % Wv;
    const float* row = x + ((size_t)bi * Lv + r * Wv + c) * Cv;
    float v[6];
#pragma unroll
    for (int k = 0; k < 6; k++) v[k] = row[lane + 32 * k];
    float s = 0.f;
#pragma unroll
    for (int k = 0; k < 6; k++) s += v[k];
#pragma unroll
    for (int o = 16; o; o >>= 1) s += __shfl_xor_sync(0xffffffffu, s, o);
    float mean = s * (1.f / 192.f);
    float q = 0.f;
#pragma unroll
    for (int k = 0; k < 6; k++) { float d = v[k] - mean; q += d * d; }
#pragma unroll
    for (int o = 16; o; o >>= 1) q += __shfl_xor_sync(0xffffffffu, q, o);
    float rstd = rsqrtf(q * (1.f / 192.f) + 1e-5f);
#pragma unroll
    for (int k = 0; k < 6; k++) {
        int cc = lane + 32 * k;
        g_hwin[(size_t)m * Cv + cc] = __float2bfloat16((v[k] - mean) * rstd * g[cc] + b[cc]);
    }
}

__global__ void ln2_kernel(const float* __restrict__ g,
                           const float* __restrict__ b) {
    int warp = threadIdx.x >> 5, lane = threadIdx.x & 31;
    int m = blockIdx.x * 8 + warp;
    const float* row = g_x1 + (size_t)m * Cv;
    float v[6];
#pragma unroll
    for (int k = 0; k < 6; k++) v[k] = row[lane + 32 * k];
    float s = 0.f;
#pragma unroll
    for (int k = 0; k < 6; k++) s += v[k];
#pragma unroll
    for (int o = 16; o; o >>= 1) s += __shfl_xor_sync(0xffffffffu, s, o);
    float mean = s * (1.f / 192.f);
    float q = 0.f;
#pragma unroll
    for (int k = 0; k < 6; k++) { float d = v[k] - mean; q += d * d; }
#pragma unroll
    for (int o = 16; o; o >>= 1) q += __shfl_xor_sync(0xffffffffu, q, o);
    float rstd = rsqrtf(q * (1.f / 192.f) + 1e-5f);
#pragma unroll
    for (int k = 0; k < 6; k++) {
        int cc = lane + 32 * k;
        g_h2n[(size_t)m * Cv + cc] = __float2bfloat16((v[k] - mean) * rstd * g[cc] + b[cc]);
    }
}

// ---------------- tensor-core attention: one block per window ----------------
__global__ __launch_bounds__(256) void attn_wmma() {
    int win = blockIdx.x;
    int wi  = win & 63;
    int tid = threadIdx.x, warp = tid >> 5, lane = tid & 31;

    __shared__ __align__(16) __nv_bfloat16 Qs[64 * 40];
    __shared__ __align__(16) __nv_bfloat16 Ks[64 * 40];
    __shared__ __align__(16) __nv_bfloat16 Vs[64 * 40];
    __shared__ __align__(16) float         Ss[64 * 68];
    __shared__ __align__(16) __nv_bfloat16 Ps[64 * 72];
    float* Os = Ss;

    for (int head = 0; head < HEADS; head++) {
        size_t base = (size_t)(win * HEADS + head) * NT * HD;
        for (int id = tid; id < 196; id += 256) {
            int r = id >> 2, c8 = (id & 3) * 8;
            *(uint4*)&Qs[r * 40 + c8] = *(const uint4*)&g_Q[base + id * 8];
            *(uint4*)&Ks[r * 40 + c8] = *(const uint4*)&g_K[base + id * 8];
            *(uint4*)&Vs[r * 40 + c8] = *(const uint4*)&g_V[base + id * 8];
        }
        for (int id = tid; id < 60; id += 256) {
            int r = 49 + (id >> 2), c8 = (id & 3) * 8;
            *(uint4*)&Vs[r * 40 + c8] = make_uint4(0, 0, 0, 0);
        }
        __syncthreads();

        {
            int mrow = (warp >> 1) * 16, ncol = (warp & 1) * 32;
            wmma::fragment<wmma::accumulator, 16, 16, 16, float> acc[2];
            wmma::fill_fragment(acc[0], 0.f);
            wmma::fill_fragment(acc[1], 0.f);
#pragma unroll
            for (int kk = 0; kk < 32; kk += 16) {
                wmma::fragment<wmma::matrix_a, 16, 16, 16, __nv_bfloat16, wmma::row_major> af;
                wmma::load_matrix_sync(af, &Qs[mrow * 40 + kk], 40);
#pragma unroll
                for (int j = 0; j < 2; j++) {
                    wmma::fragment<wmma::matrix_b, 16, 16, 16, __nv_bfloat16, wmma::col_major> bf;
                    wmma::load_matrix_sync(bf, &Ks[(ncol + j * 16) * 40 + kk], 40);
                    wmma::mma_sync(acc[j], af, bf, acc[j]);
                }
            }
#pragma unroll
            for (int j = 0; j < 2; j++)
                wmma::store_matrix_sync(&Ss[mrow * 68 + ncol + j * 16], acc[j], 68,
                                        wmma::mem_row_major);
        }
        __syncthreads();

        {
            const float* bmp = g_bm + (size_t)(wi * HEADS + head) * (NT * NT);
            for (int row = warp; row < NT; row += 8) {
                int j1 = lane + 32;
                float s0 = Ss[row * 68 + lane] + bmp[row * NT + lane];
                float s1 = (j1 < NT) ? Ss[row * 68 + j1] + bmp[row * NT + j1] : -1e30f;
                float mx = fmaxf(s0, s1);
#pragma unroll
                for (int o = 16; o; o >>= 1) mx = fmaxf(mx, __shfl_xor_sync(0xffffffffu, mx, o));
                float e0 = __expf(s0 - mx);
                float e1 = (j1 < NT) ? __expf(s1 - mx) : 0.f;
                float sm = e0 + e1;
#pragma unroll
                for (int o = 16; o; o >>= 1) sm += __shfl_xor_sync(0xffffffffu, sm, o);
                float inv = 1.f / sm;
                Ps[row * 72 + lane] = __float2bfloat16(e0 * inv);
                Ps[row * 72 + j1]   = __float2bfloat16(e1 * inv);
            }
        }
        __syncthreads();

        {
            int mrow = (warp >> 1) * 16, ncol = (warp & 1) * 16;
            wmma::fragment<wmma::accumulator, 16, 16, 16, float> acc;
            wmma::fill_fragment(acc, 0.f);
#pragma unroll
            for (int kk = 0; kk < 64; kk += 16) {
                wmma::fragment<wmma::matrix_a, 16, 16, 16, __nv_bfloat16, wmma::row_major> af;
                wmma::fragment<wmma::matrix_b, 16, 16, 16, __nv_bfloat16, wmma::row_major> bf;
                wmma::load_matrix_sync(af, &Ps[mrow * 72 + kk], 72);
                wmma::load_matrix_sync(bf, &Vs[kk * 40 + ncol], 40);
                wmma::mma_sync(acc, af, bf, acc);
            }
            wmma::store_matrix_sync(&Os[mrow * 36 + ncol], acc, 36, wmma::mem_row_major);
        }
        __syncthreads();

        if (tid < 98) {
            int r = tid >> 1, d0 = (tid & 1) * 16;
            __nv_bfloat16* dst = &g_attn[((size_t)win * NT + r) * Cv + head * HD + d0];
            const float* src = &Os[r * 36 + d0];
#pragma unroll
            for (int cc = 0; cc < 16; cc += 8) {
                float4 a = *(const float4*)&src[cc];
                float4 b = *(const float4*)&src[cc + 4];
                __nv_bfloat16 o[8] = {
                    __float2bfloat16(a.x), __float2bfloat16(a.y),
                    __float2bfloat16(a.z), __float2bfloat16(a.w),
                    __float2bfloat16(b.x), __float2bfloat16(b.y),
                    __float2bfloat16(b.z), __float2bfloat16(b.w)};
                *(uint4*)&dst[cc] = *(const uint4*)o;
            }
        }
        __syncthreads();
    }
}

// ---------------- pipelined bf16 wmma GEMM, wide warp tiles, 1 sync/iter -----
// Dynamic smem (may exceed 48KB static limit for NTL>=96).
template <int EPI, int NTL>
__global__ __launch_bounds__(256) void gemm_k(const float* __restrict__ bias,
                                              const float* __restrict__ xin,
                                              float* __restrict__ outf) {
    constexpr int K  = (EPI == 3) ? MLPD : Cv;
    constexpr int N  = (EPI == 0) ? 3 * Cv : (EPI == 2) ? MLPD : Cv;
    constexpr int BK = 32;
    constexpr int NK = K / BK;
    constexpr int WN  = NTL / 2;       // warp N-extent (4x2 warp grid)
    constexpr int NFR = WN / 16;       // B fragments per warp
    constexpr int BST = NTL + 8;       // B smem stride
    constexpr int CST = NTL + 4;       // C smem stride
    constexpr int ASZ = 128 * 40;      // A stage elems
    constexpr int BSZ = 32 * BST;      // B stage elems

    const __nv_bfloat16* __restrict__ A =
        (EPI == 0) ? g_hwin : (EPI == 1) ? g_attn : (EPI == 2) ? g_h2n : g_mid;
    const __nv_bfloat16* __restrict__ Bm =
        (EPI == 0) ? g_wqkv : (EPI == 1) ? g_wproj : (EPI == 2) ? g_w1 : g_w2;

    extern __shared__ __align__(16) unsigned char smbuf[];
    __nv_bfloat16* As = (__nv_bfloat16*)smbuf;
    __nv_bfloat16* Bs = (__nv_bfloat16*)(smbuf + 3 * ASZ * 2);
    float*         Cs = (float*)smbuf;

    const int tid = threadIdx.x;
    const int m0 = blockIdx.y * 128;
    const int n0 = blockIdx.x * NTL;
    const int warp = tid >> 5, wm = warp >> 1, wn = warp & 1;

    auto load_stage = [&](int kt, int stg) {
        int k0 = kt * BK;
        __nv_bfloat16* as = As + stg * ASZ;
        __nv_bfloat16* bs = Bs + stg * BSZ;
#pragma unroll
        for (int i = 0; i < 2; i++) {
            int id = tid + i * 256;
            int r = id >> 2, c8 = (id & 3) * 8;
            cp16(&as[r * 40 + c8], &A[(size_t)(m0 + r) * K + k0 + c8]);
        }
        for (int id = tid; id < 32 * (NTL / 8); id += 256) {
            int r = id / (NTL / 8), c8 = (id % (NTL / 8)) * 8;
            cp16(&bs[r * BST + c8], &Bm[(size_t)(k0 + r) * N + n0 + c8]);
        }
    };

    wmma::fragment<wmma::accumulator, 16, 16, 16, float> acc[2][NFR];
#pragma unroll
    for (int i = 0; i < 2; i++)
#pragma unroll
        for (int j = 0; j < NFR; j++) wmma::fill_fragment(acc[i][j], 0.f);

    load_stage(0, 0); CP_COMMIT();
    load_stage(1, 1); CP_COMMIT();

    for (int kt = 0; kt < NK; kt++) {
        CP_WAIT1();
        __syncthreads();
        const __nv_bfloat16* as = As + (kt % 3) * ASZ;
        const __nv_bfloat16* bs = Bs + (kt % 3) * BSZ;
#pragma unroll
        for (int kk = 0; kk < BK; kk += 16) {
            wmma::fragment<wmma::matrix_a, 16, 16, 16, __nv_bfloat16, wmma::row_major> af[2];
            wmma::fragment<wmma::matrix_b, 16, 16, 16, __nv_bfloat16, wmma::row_major> bfr[NFR];
            wmma::load_matrix_sync(af[0], &as[(wm * 32 + 0)  * 40 + kk], 40);
            wmma::load_matrix_sync(af[1], &as[(wm * 32 + 16) * 40 + kk], 40);
#pragma unroll
            for (int j = 0; j < NFR; j++)
                wmma::load_matrix_sync(bfr[j], &bs[kk * BST + wn * WN + j * 16], BST);
#pragma unroll
            for (int i = 0; i < 2; i++)
#pragma unroll
                for (int j = 0; j < NFR; j++)
                    wmma::mma_sync(acc[i][j], af[i], bfr[j], acc[i][j]);
        }
        if (kt + 2 < NK) load_stage(kt + 2, (kt + 2) % 3);
        CP_COMMIT();
    }
    __syncthreads();   // all compute done before Cs overwrites stage smem

#pragma unroll
    for (int i = 0; i < 2; i++)
#pragma unroll
        for (int j = 0; j < NFR; j++)
            wmma::store_matrix_sync(&Cs[(wm * 32 + i * 16) * CST + wn * WN + j * 16],
                                    acc[i][j], CST, wmma::mem_row_major);
    __syncthreads();

    // -------- epilogue: per-8-element chunks (never cross head/sel bounds) ---
    for (int e = tid; e < 128 * (NTL / 8); e += 256) {
        int r  = e / (NTL / 8);
        int c8 = (e % (NTL / 8)) * 8;
        int m  = m0 + r;
        int nb = n0 + c8;
        const float* crow = &Cs[r * CST + c8];
        float4 a = *(const float4*)&crow[0];
        float4 bq = *(const float4*)&crow[4];
        float4 ba = *(const float4*)&bias[nb];
        float4 bb = *(const float4*)&bias[nb + 4];
        float vv[8] = {a.x + ba.x, a.y + ba.y, a.z + ba.z, a.w + ba.w,
                       bq.x + bb.x, bq.y + bb.y, bq.z + bb.z, bq.w + bb.w};

        if constexpr (EPI == 0) {
            int sel  = nb / Cv;
            int w2   = nb - sel * Cv;
            int head = w2 >> 5, d = w2 & 31;
            int win = m / NT, tok = m - win * NT;
            __nv_bfloat16* dst =
                (sel == 0 ? g_Q : sel == 1 ? g_K : g_V) +
                ((size_t)(win * HEADS + head) * NT + tok) * HD + d;
            const float sc = (sel == 0) ? SCALE : 1.f;
            __nv_bfloat16 o[8];
#pragma unroll
            for (int u = 0; u < 8; u++) o[u] = __float2bfloat16(vv[u] * sc);
            *(uint4*)dst = *(const uint4*)o;
        } else if constexpr (EPI == 1) {
            int win = m / NT, tok = m - win * NT;
            int bi = win >> 6, wi = win & 63;
            int wh = wi >> 3, ww = wi & 7;
            int ih = tok / WS, iw = tok - ih * WS;
            int r2 = (wh * WS + ih + SS) % Hv;
            int c2 = (ww * WS + iw + SS) % Wv;
            size_t pos = ((size_t)bi * Lv + r2 * Wv + c2) * Cv + nb;
#pragma unroll
            for (int u = 0; u < 8; u += 4) {
                float4 xv = *(const float4*)&xin[pos + u];
                float4 o = make_float4(vv[u] + xv.x, vv[u + 1] + xv.y,
                                       vv[u + 2] + xv.z, vv[u + 3] + xv.w);
                *(float4*)&g_x1[pos + u] = o;
            }
        } else if constexpr (EPI == 2) {
            size_t pos = (size_t)m * MLPD + nb;
            __nv_bfloat16 o[8];
#pragma unroll
            for (int u = 0; u < 8; u++) {
                float t = vv[u];
                o[u] = __float2bfloat16(0.5f * t * (1.f + erff(t * 0.70710678118654752f)));
            }
            *(uint4*)&g_mid[pos] = *(const uint4*)o;
        } else {
            size_t pos = (size_t)m * Cv + nb;
#pragma unroll
            for (int u = 0; u < 8; u += 4) {
                float4 xv = *(const float4*)&g_x1[pos + u];
                float4 o = make_float4(vv[u] + xv.x, vv[u + 1] + xv.y,
                                       vv[u + 2] + xv.z, vv[u + 3] + xv.w);
                *(float4*)&outf[pos + u] = o;
            }
        }
    }
}

// ---------------- launch ----------------
extern "C" void kernel_launch(void* const* d_in, const int* in_sizes, int n_in,
                              void* d_out, int out_size) {
    const float* x      = (const float*)d_in[0];
    const float* ln1_g  = (const float*)d_in[1];
    const float* ln1_b  = (const float*)d_in[2];
    const float* qkv_w  = (const float*)d_in[3];
    const float* qkv_b  = (const float*)d_in[4];
    const float* proj_w = (const float*)d_in[5];
    const float* proj_b = (const float*)d_in[6];
    const float* rpb    = (const float*)d_in[7];
    const float* ln2_g  = (const float*)d_in[8];
    const float* ln2_b  = (const float*)d_in[9];
    const float* mlp_w1 = (const float*)d_in[10];
    const float* mlp_b1 = (const float*)d_in[11];
    const float* mlp_w2 = (const float*)d_in[12];
    const float* mlp_b2 = (const float*)d_in[13];
    float* out = (float*)d_out;

    constexpr size_t S96  = gemm_smem(96);
    constexpr size_t S64  = gemm_smem(64);
    constexpr size_t S128 = gemm_smem(128);
    cudaFuncSetAttribute(gemm_k<0, 96>,  cudaFuncAttributeMaxDynamicSharedMemorySize, (int)S96);
    cudaFuncSetAttribute(gemm_k<1, 64>,  cudaFuncAttributeMaxDynamicSharedMemorySize, (int)S64);
    cudaFuncSetAttribute(gemm_k<2, 128>, cudaFuncAttributeMaxDynamicSharedMemorySize, (int)S128);
    cudaFuncSetAttribute(gemm_k<3, 64>,  cudaFuncAttributeMaxDynamicSharedMemorySize, (int)S64);

    cvt_weights<<<432, 1024>>>(qkv_w, proj_w, mlp_w1, mlp_w2);
    bm_kernel<<<(64 * HEADS * NT * NT + 255) / 256, 256>>>(rpb);
    ln1_kernel<<<MT / 8, 256>>>(x, ln1_g, ln1_b);
    gemm_k<0, 96><<<dim3(576 / 96, MT / 128), 256, S96>>>(qkv_b, nullptr, nullptr);
    attn_wmma<<<Bv * 64, 256>>>();
    gemm_k<1, 64><<<dim3(192 / 64, MT / 128), 256, S64>>>(proj_b, x, nullptr);
    ln2_kernel<<<MT / 8, 256>>>(ln2_g, ln2_b);
    gemm_k<2, 128><<<dim3(768 / 128, MT / 128), 256, S128>>>(mlp_b1, nullptr, nullptr);
    gemm_k<3, 64><<<dim3(192 / 64, MT / 128), 256, S64>>>(mlp_b2, nullptr, out);
}

// round 11
// speedup vs baseline: 1.2841x; 1.0523x over previous
#include <cuda_runtime.h>
#include <cuda_bf16.h>
#include <mma.h>
#include <cstdint>

using namespace nvcuda;

// ---------------- problem constants ----------------
constexpr int Bv   = 64;
constexpr int Hv   = 56;
constexpr int Wv   = 56;
constexpr int Cv   = 192;
constexpr int HEADS= 6;
constexpr int WS   = 7;
constexpr int SS   = 3;
constexpr int MLPD = 768;
constexpr int NT   = 49;
constexpr int HD   = 32;
constexpr int Lv   = Hv * Wv;         // 3136
constexpr int MT   = Bv * Lv;         // 200704 rows
constexpr float SCALE = 0.17677669529663687f;

// ---------------- device scratch ----------------
__device__ __nv_bfloat16 g_hwin[(size_t)MT * Cv];
__device__ __nv_bfloat16 g_Q[(size_t)MT * Cv];
__device__ __nv_bfloat16 g_K[(size_t)MT * Cv];
__device__ __nv_bfloat16 g_V[(size_t)MT * Cv];
__device__ __nv_bfloat16 g_attn[(size_t)MT * Cv];
__device__ float         g_x1[(size_t)MT * Cv];
__device__ __nv_bfloat16 g_h2n[(size_t)MT * Cv];
__device__ __nv_bfloat16 g_mid[(size_t)MT * MLPD];
__device__ __nv_bfloat16 g_wqkv[Cv * 3 * Cv];   // row-major [K][N]
__device__ __nv_bfloat16 g_wproj[Cv * Cv];
__device__ __nv_bfloat16 g_w1[Cv * MLPD];
__device__ __nv_bfloat16 g_w2[MLPD * Cv];
__device__ float         g_bmp[64 * HEADS * NT * 52];  // bias+mask, padded stride 52

// ---------------- cp.async helpers ----------------
__device__ __forceinline__ void cp16(void* d, const void* s) {
    unsigned sa = (unsigned)__cvta_generic_to_shared(d);
    asm volatile("cp.async.cg.shared.global [%0], [%1], 16;" :: "r"(sa), "l"(s));
}
#define CP_COMMIT() asm volatile("cp.async.commit_group;")
#define CP_WAIT0()  asm volatile("cp.async.wait_group 0;")
#define CP_WAIT1()  asm volatile("cp.async.wait_group 1;")

// ---------------- weight conversion fp32 -> bf16 (row-major) ----------------
__global__ void cvt_weights(const float* __restrict__ qkvw,
                            const float* __restrict__ projw,
                            const float* __restrict__ w1,
                            const float* __restrict__ w2) {
    constexpr int n0 = Cv * 3 * Cv;
    constexpr int n1 = Cv * Cv;
    constexpr int n2 = Cv * MLPD;
    constexpr int n3 = MLPD * Cv;
    constexpr int tot = n0 + n1 + n2 + n3;
    for (int i = blockIdx.x * blockDim.x + threadIdx.x; i < tot;
         i += gridDim.x * blockDim.x) {
        if (i < n0)                  g_wqkv[i]             = __float2bfloat16(qkvw[i]);
        else if (i < n0 + n1)        g_wproj[i - n0]       = __float2bfloat16(projw[i - n0]);
        else if (i < n0 + n1 + n2)   g_w1[i - n0 - n1]     = __float2bfloat16(w1[i - n0 - n1]);
        else                         g_w2[i - n0 - n1 - n2]= __float2bfloat16(w2[i - n0 - n1 - n2]);
    }
}

// ---------------- shift-mask + padded bias table ----------------
__device__ __forceinline__ int reg3(int r) { return r < 49 ? 0 : (r < 53 ? 1 : 2); }

__global__ void bm_kernel(const float* __restrict__ rpb) {
    int e = blockIdx.x * blockDim.x + threadIdx.x;
    constexpr int TOT = 64 * HEADS * NT * 52;
    if (e >= TOT) return;
    int j   = e % 52;
    int i   = (e / 52) % NT;
    int h   = (e / (52 * NT)) % HEADS;
    int wi  = e / (52 * NT * HEADS);
    float v = 0.f;
    if (j < NT) {
        int wh = wi >> 3, ww = wi & 7;
        int ih = i / WS, iw = i - ih * WS;
        int jh = j / WS, jw = j - jh * WS;
        int idx = (ih - jh + WS - 1) * (2 * WS - 1) + (iw - jw + WS - 1);
        v = rpb[idx * HEADS + h];
        int li = reg3(wh * WS + ih) * 3 + reg3(ww * WS + iw);
        int lj = reg3(wh * WS + jh) * 3 + reg3(ww * WS + jw);
        if (li != lj) v -= 100.f;
    }
    g_bmp[e] = v;
}

// ---------------- LayerNorm kernels ----------------
__global__ void ln1_kernel(const float* __restrict__ x,
                           const float* __restrict__ g,
                           const float* __restrict__ b) {
    int warp = threadIdx.x >> 5, lane = threadIdx.x & 31;
    int m = blockIdx.x * 8 + warp;
    int win = m / NT, tok = m - win * NT;
    int bi  = win >> 6, wi = win & 63;
    int wh  = wi >> 3, ww = wi & 7;
    int ih  = tok / WS, iw = tok - ih * WS;
    int r   = (wh * WS + ih + SS) % Hv;
    int c   = (ww * WS + iw + SS) % Wv;
    const float* row = x + ((size_t)bi * Lv + r * Wv + c) * Cv;
    float v[6];
#pragma unroll
    for (int k = 0; k < 6; k++) v[k] = row[lane + 32 * k];
    float s = 0.f;
#pragma unroll
    for (int k = 0; k < 6; k++) s += v[k];
#pragma unroll
    for (int o = 16; o; o >>= 1) s += __shfl_xor_sync(0xffffffffu, s, o);
    float mean = s * (1.f / 192.f);
    float q = 0.f;
#pragma unroll
    for (int k = 0; k < 6; k++) { float d = v[k] - mean; q += d * d; }
#pragma unroll
    for (int o = 16; o; o >>= 1) q += __shfl_xor_sync(0xffffffffu, q, o);
    float rstd = rsqrtf(q * (1.f / 192.f) + 1e-5f);
#pragma unroll
    for (int k = 0; k < 6; k++) {
        int cc = lane + 32 * k;
        g_hwin[(size_t)m * Cv + cc] = __float2bfloat16((v[k] - mean) * rstd * g[cc] + b[cc]);
    }
}

__global__ void ln2_kernel(const float* __restrict__ g,
                           const float* __restrict__ b) {
    int warp = threadIdx.x >> 5, lane = threadIdx.x & 31;
    int m = blockIdx.x * 8 + warp;
    const float* row = g_x1 + (size_t)m * Cv;
    float v[6];
#pragma unroll
    for (int k = 0; k < 6; k++) v[k] = row[lane + 32 * k];
    float s = 0.f;
#pragma unroll
    for (int k = 0; k < 6; k++) s += v[k];
#pragma unroll
    for (int o = 16; o; o >>= 1) s += __shfl_xor_sync(0xffffffffu, s, o);
    float mean = s * (1.f / 192.f);
    float q = 0.f;
#pragma unroll
    for (int k = 0; k < 6; k++) { float d = v[k] - mean; q += d * d; }
#pragma unroll
    for (int o = 16; o; o >>= 1) q += __shfl_xor_sync(0xffffffffu, q, o);
    float rstd = rsqrtf(q * (1.f / 192.f) + 1e-5f);
#pragma unroll
    for (int k = 0; k < 6; k++) {
        int cc = lane + 32 * k;
        g_h2n[(size_t)m * Cv + cc] = __float2bfloat16((v[k] - mean) * rstd * g[cc] + b[cc]);
    }
}

// ---------------- attention: one block/window, cp.async head pipelining -----
// dynamic smem layout (bytes):
//   Qs 0..5120, Ks 5120.., Vs 10240.., Ss/Os 15360 (64*68 f32),
//   Ps 32768 (64*72 bf16), Bms 41984 (49*52 f32)  -> total 52176
constexpr int ATTN_SMEM = 52176;

__global__ __launch_bounds__(256) void attn_wmma() {
    extern __shared__ __align__(16) unsigned char sm[];
    __nv_bfloat16* Qs = (__nv_bfloat16*)(sm);
    __nv_bfloat16* Ks = (__nv_bfloat16*)(sm + 5120);
    __nv_bfloat16* Vs = (__nv_bfloat16*)(sm + 10240);
    float*         Ss = (float*)(sm + 15360);
    __nv_bfloat16* Ps = (__nv_bfloat16*)(sm + 32768);
    float*         Bms= (float*)(sm + 41984);
    float*         Os = Ss;

    int win = blockIdx.x;
    int wi  = win & 63;
    int tid = threadIdx.x, warp = tid >> 5, lane = tid & 31;

    auto loadQK = [&](int head) {
        size_t base = (size_t)(win * HEADS + head) * NT * HD;
        for (int id = tid; id < 196; id += 256) {
            int r = id >> 2, c8 = (id & 3) * 8;
            cp16(&Qs[r * 40 + c8], &g_Q[base + id * 8]);
            cp16(&Ks[r * 40 + c8], &g_K[base + id * 8]);
        }
    };
    auto loadV = [&](int head) {
        size_t base = (size_t)(win * HEADS + head) * NT * HD;
        for (int id = tid; id < 196; id += 256) {
            int r = id >> 2, c8 = (id & 3) * 8;
            cp16(&Vs[r * 40 + c8], &g_V[base + id * 8]);
        }
    };
    auto loadBM = [&](int head) {
        const float* src = g_bmp + (size_t)(wi * HEADS + head) * (NT * 52);
        for (int id = tid; id < 49 * 13; id += 256) {
            int r = id / 13, c4 = (id % 13) * 4;
            cp16(&Bms[r * 52 + c4], &src[r * 52 + c4]);
        }
    };

    // prologue: zero V pad rows once, prefetch head 0
    for (int id = tid; id < 60; id += 256) {
        int r = 49 + (id >> 2), c8 = (id & 3) * 8;
        *(uint4*)&Vs[r * 40 + c8] = make_uint4(0, 0, 0, 0);
    }
    __syncthreads();
    loadQK(0); loadV(0); loadBM(0); CP_COMMIT();

    for (int head = 0; head < HEADS; head++) {
        CP_WAIT0();
        __syncthreads();                                   // [1] data ready / Os free

        // S = Q @ K^T (64x64x32)
        {
            int mrow = (warp >> 1) * 16, ncol = (warp & 1) * 32;
            wmma::fragment<wmma::accumulator, 16, 16, 16, float> acc[2];
            wmma::fill_fragment(acc[0], 0.f);
            wmma::fill_fragment(acc[1], 0.f);
#pragma unroll
            for (int kk = 0; kk < 32; kk += 16) {
                wmma::fragment<wmma::matrix_a, 16, 16, 16, __nv_bfloat16, wmma::row_major> af;
                wmma::load_matrix_sync(af, &Qs[mrow * 40 + kk], 40);
#pragma unroll
                for (int j = 0; j < 2; j++) {
                    wmma::fragment<wmma::matrix_b, 16, 16, 16, __nv_bfloat16, wmma::col_major> bf;
                    wmma::load_matrix_sync(bf, &Ks[(ncol + j * 16) * 40 + kk], 40);
                    wmma::mma_sync(acc[j], af, bf, acc[j]);
                }
            }
#pragma unroll
            for (int j = 0; j < 2; j++)
                wmma::store_matrix_sync(&Ss[mrow * 68 + ncol + j * 16], acc[j], 68,
                                        wmma::mem_row_major);
        }
        __syncthreads();                                   // [2] Qs/Ks consumed
        if (head + 1 < HEADS) { loadQK(head + 1); CP_COMMIT(); }

        // softmax rows 0..48 with smem bias+mask
        for (int row = warp; row < NT; row += 8) {
            int j1 = lane + 32;
            float s0 = Ss[row * 68 + lane] + Bms[row * 52 + lane];
            float s1 = (j1 < NT) ? Ss[row * 68 + j1] + Bms[row * 52 + j1] : -1e30f;
            float mx = fmaxf(s0, s1);
#pragma unroll
            for (int o = 16; o; o >>= 1) mx = fmaxf(mx, __shfl_xor_sync(0xffffffffu, mx, o));
            float e0 = __expf(s0 - mx);
            float e1 = (j1 < NT) ? __expf(s1 - mx) : 0.f;
            float smv = e0 + e1;
#pragma unroll
            for (int o = 16; o; o >>= 1) smv += __shfl_xor_sync(0xffffffffu, smv, o);
            float inv = 1.f / smv;
            Ps[row * 72 + lane] = __float2bfloat16(e0 * inv);
            Ps[row * 72 + j1]   = __float2bfloat16(e1 * inv);
        }
        __syncthreads();                                   // [3] Bms consumed / Ps ready
        if (head + 1 < HEADS) { loadBM(head + 1); CP_COMMIT(); }

        // O = P @ V (64x32x64)
        {
            int mrow = (warp >> 1) * 16, ncol = (warp & 1) * 16;
            wmma::fragment<wmma::accumulator, 16, 16, 16, float> acc;
            wmma::fill_fragment(acc, 0.f);
#pragma unroll
            for (int kk = 0; kk < 64; kk += 16) {
                wmma::fragment<wmma::matrix_a, 16, 16, 16, __nv_bfloat16, wmma::row_major> af;
                wmma::fragment<wmma::matrix_b, 16, 16, 16, __nv_bfloat16, wmma::row_major> bf;
                wmma::load_matrix_sync(af, &Ps[mrow * 72 + kk], 72);
                wmma::load_matrix_sync(bf, &Vs[kk * 40 + ncol], 40);
                wmma::mma_sync(acc, af, bf, acc);
            }
            wmma::store_matrix_sync(&Os[mrow * 36 + ncol], acc, 36, wmma::mem_row_major);
        }
        __syncthreads();                                   // [4] Vs consumed / Os ready
        if (head + 1 < HEADS) { loadV(head + 1); CP_COMMIT(); }

        // write O rows < 49 (196 threads, 8 cols each)
        if (tid < 196) {
            int r = tid >> 2, d0 = (tid & 3) * 8;
            const float* src = &Os[r * 36 + d0];
            float4 a = *(const float4*)&src[0];
            float4 b = *(const float4*)&src[4];
            __nv_bfloat16 o[8] = {
                __float2bfloat16(a.x), __float2bfloat16(a.y),
                __float2bfloat16(a.z), __float2bfloat16(a.w),
                __float2bfloat16(b.x), __float2bfloat16(b.y),
                __float2bfloat16(b.z), __float2bfloat16(b.w)};
            *(uint4*)&g_attn[((size_t)win * NT + r) * Cv + head * HD + d0] =
                *(const uint4*)o;
        }
        // next iteration's sync [1] orders these reads before Os reuse
    }
}

// ---------------- whole-K wmma GEMM for K=192 (one load, no mainloop sync) --
// EPI 0: hwin @ wqkv (NTL=96), EPI 1: attn @ wproj (NTL=64), EPI 2: h2n @ w1 (NTL=128)
template <int EPI, int NTL>
__global__ __launch_bounds__(256) void gemm_wk(const float* __restrict__ bias,
                                               const float* __restrict__ xin) {
    constexpr int K   = Cv;            // 192
    constexpr int N   = (EPI == 0) ? 3 * Cv : (EPI == 2) ? MLPD : Cv;
    constexpr int WN  = NTL / 2;
    constexpr int NFR = WN / 16;
    constexpr int ASTR= K + 8;         // 200
    constexpr int BSTR= NTL + 8;
    constexpr int CST = NTL + 4;

    const __nv_bfloat16* __restrict__ A =
        (EPI == 0) ? g_hwin : (EPI == 1) ? g_attn : g_h2n;
    const __nv_bfloat16* __restrict__ Bm =
        (EPI == 0) ? g_wqkv : (EPI == 1) ? g_wproj : g_w1;

    extern __shared__ __align__(16) unsigned char smbuf[];
    __nv_bfloat16* As = (__nv_bfloat16*)smbuf;                     // [128][ASTR]
    __nv_bfloat16* Bs = (__nv_bfloat16*)(smbuf + 128 * ASTR * 2);  // [192][BSTR]
    float*         Cs = (float*)smbuf;                             // [128][CST]

    const int tid = threadIdx.x;
    const int m0 = blockIdx.y * 128;
    const int n0 = blockIdx.x * NTL;
    const int warp = tid >> 5, wm = warp >> 1, wn = warp & 1;

    // single load phase (whole K)
    for (int id = tid; id < 128 * (K / 8); id += 256) {
        int r = id / (K / 8), c8 = (id % (K / 8)) * 8;
        cp16(&As[r * ASTR + c8], &A[(size_t)(m0 + r) * K + c8]);
    }
    for (int id = tid; id < K * (NTL / 8); id += 256) {
        int r = id / (NTL / 8), c8 = (id % (NTL / 8)) * 8;
        cp16(&Bs[r * BSTR + c8], &Bm[(size_t)r * N + n0 + c8]);
    }
    CP_COMMIT();
    CP_WAIT0();
    __syncthreads();

    wmma::fragment<wmma::accumulator, 16, 16, 16, float> acc[2][NFR];
#pragma unroll
    for (int i = 0; i < 2; i++)
#pragma unroll
        for (int j = 0; j < NFR; j++) wmma::fill_fragment(acc[i][j], 0.f);

#pragma unroll
    for (int kk = 0; kk < K; kk += 16) {
        wmma::fragment<wmma::matrix_a, 16, 16, 16, __nv_bfloat16, wmma::row_major> af[2];
        wmma::fragment<wmma::matrix_b, 16, 16, 16, __nv_bfloat16, wmma::row_major> bfr[NFR];
        wmma::load_matrix_sync(af[0], &As[(wm * 32 + 0)  * ASTR + kk], ASTR);
        wmma::load_matrix_sync(af[1], &As[(wm * 32 + 16) * ASTR + kk], ASTR);
#pragma unroll
        for (int j = 0; j < NFR; j++)
            wmma::load_matrix_sync(bfr[j], &Bs[kk * BSTR + wn * WN + j * 16], BSTR);
#pragma unroll
        for (int i = 0; i < 2; i++)
#pragma unroll
            for (int j = 0; j < NFR; j++)
                wmma::mma_sync(acc[i][j], af[i], bfr[j], acc[i][j]);
    }
    __syncthreads();   // all reads of As/Bs done before Cs overwrite

#pragma unroll
    for (int i = 0; i < 2; i++)
#pragma unroll
        for (int j = 0; j < NFR; j++)
            wmma::store_matrix_sync(&Cs[(wm * 32 + i * 16) * CST + wn * WN + j * 16],
                                    acc[i][j], CST, wmma::mem_row_major);
    __syncthreads();

    for (int e = tid; e < 128 * (NTL / 8); e += 256) {
        int r  = e / (NTL / 8);
        int c8 = (e % (NTL / 8)) * 8;
        int m  = m0 + r;
        int nb = n0 + c8;
        const float* crow = &Cs[r * CST + c8];
        float4 a = *(const float4*)&crow[0];
        float4 bq = *(const float4*)&crow[4];
        float4 ba = *(const float4*)&bias[nb];
        float4 bb = *(const float4*)&bias[nb + 4];
        float vv[8] = {a.x + ba.x, a.y + ba.y, a.z + ba.z, a.w + ba.w,
                       bq.x + bb.x, bq.y + bb.y, bq.z + bb.z, bq.w + bb.w};

        if constexpr (EPI == 0) {
            int sel  = nb / Cv;
            int w2   = nb - sel * Cv;
            int head = w2 >> 5, d = w2 & 31;
            int win = m / NT, tok = m - win * NT;
            __nv_bfloat16* dst =
                (sel == 0 ? g_Q : sel == 1 ? g_K : g_V) +
                ((size_t)(win * HEADS + head) * NT + tok) * HD + d;
            const float sc = (sel == 0) ? SCALE : 1.f;
            __nv_bfloat16 o[8];
#pragma unroll
            for (int u = 0; u < 8; u++) o[u] = __float2bfloat16(vv[u] * sc);
            *(uint4*)dst = *(const uint4*)o;
        } else if constexpr (EPI == 1) {
            int win = m / NT, tok = m - win * NT;
            int bi = win >> 6, wi = win & 63;
            int wh = wi >> 3, ww = wi & 7;
            int ih = tok / WS, iw = tok - ih * WS;
            int r2 = (wh * WS + ih + SS) % Hv;
            int c2 = (ww * WS + iw + SS) % Wv;
            size_t pos = ((size_t)bi * Lv + r2 * Wv + c2) * Cv + nb;
#pragma unroll
            for (int u = 0; u < 8; u += 4) {
                float4 xv = *(const float4*)&xin[pos + u];
                float4 o = make_float4(vv[u] + xv.x, vv[u + 1] + xv.y,
                                       vv[u + 2] + xv.z, vv[u + 3] + xv.w);
                *(float4*)&g_x1[pos + u] = o;
            }
        } else {
            size_t pos = (size_t)m * MLPD + nb;
            __nv_bfloat16 o[8];
#pragma unroll
            for (int u = 0; u < 8; u++) {
                float t = vv[u];
                o[u] = __float2bfloat16(0.5f * t * (1.f + erff(t * 0.70710678118654752f)));
            }
            *(uint4*)&g_mid[pos] = *(const uint4*)o;
        }
    }
}

constexpr size_t wk_smem(int NTL) {
    size_t lb = 128ull * (Cv + 8) * 2 + (size_t)Cv * (NTL + 8) * 2;
    size_t cb = 128ull * (NTL + 4) * 4;
    return lb > cb ? lb : cb;
}

// ---------------- pipelined wmma GEMM for K=768 (gemm3) ----------------
constexpr size_t gemm_smem(int NTL) {
    size_t stages = 3ull * (128 * 40 + 32 * (NTL + 8)) * 2;
    size_t cs     = 128ull * (NTL + 4) * 4;
    return stages > cs ? stages : cs;
}

template <int NTL>
__global__ __launch_bounds__(256) void gemm3_k(const float* __restrict__ bias,
                                               float* __restrict__ outf) {
    constexpr int K  = MLPD;
    constexpr int N  = Cv;
    constexpr int BK = 32;
    constexpr int NK = K / BK;
    constexpr int WN  = NTL / 2;
    constexpr int NFR = WN / 16;
    constexpr int BST = NTL + 8;
    constexpr int CST = NTL + 4;
    constexpr int ASZ = 128 * 40;
    constexpr int BSZ = 32 * BST;

    const __nv_bfloat16* __restrict__ A = g_mid;
    const __nv_bfloat16* __restrict__ Bm = g_w2;

    extern __shared__ __align__(16) unsigned char smbuf[];
    __nv_bfloat16* As = (__nv_bfloat16*)smbuf;
    __nv_bfloat16* Bs = (__nv_bfloat16*)(smbuf + 3 * ASZ * 2);
    float*         Cs = (float*)smbuf;

    const int tid = threadIdx.x;
    const int m0 = blockIdx.y * 128;
    const int n0 = blockIdx.x * NTL;
    const int warp = tid >> 5, wm = warp >> 1, wn = warp & 1;

    auto load_stage = [&](int kt, int stg) {
        int k0 = kt * BK;
        __nv_bfloat16* as = As + stg * ASZ;
        __nv_bfloat16* bs = Bs + stg * BSZ;
#pragma unroll
        for (int i = 0; i < 2; i++) {
            int id = tid + i * 256;
            int r = id >> 2, c8 = (id & 3) * 8;
            cp16(&as[r * 40 + c8], &A[(size_t)(m0 + r) * K + k0 + c8]);
        }
        for (int id = tid; id < 32 * (NTL / 8); id += 256) {
            int r = id / (NTL / 8), c8 = (id % (NTL / 8)) * 8;
            cp16(&bs[r * BST + c8], &Bm[(size_t)(k0 + r) * N + n0 + c8]);
        }
    };

    wmma::fragment<wmma::accumulator, 16, 16, 16, float> acc[2][NFR];
#pragma unroll
    for (int i = 0; i < 2; i++)
#pragma unroll
        for (int j = 0; j < NFR; j++) wmma::fill_fragment(acc[i][j], 0.f);

    load_stage(0, 0); CP_COMMIT();
    load_stage(1, 1); CP_COMMIT();

    for (int kt = 0; kt < NK; kt++) {
        CP_WAIT1();
        __syncthreads();
        const __nv_bfloat16* as = As + (kt % 3) * ASZ;
        const __nv_bfloat16* bs = Bs + (kt % 3) * BSZ;
#pragma unroll
        for (int kk = 0; kk < BK; kk += 16) {
            wmma::fragment<wmma::matrix_a, 16, 16, 16, __nv_bfloat16, wmma::row_major> af[2];
            wmma::fragment<wmma::matrix_b, 16, 16, 16, __nv_bfloat16, wmma::row_major> bfr[NFR];
            wmma::load_matrix_sync(af[0], &as[(wm * 32 + 0)  * 40 + kk], 40);
            wmma::load_matrix_sync(af[1], &as[(wm * 32 + 16) * 40 + kk], 40);
#pragma unroll
            for (int j = 0; j < NFR; j++)
                wmma::load_matrix_sync(bfr[j], &bs[kk * BST + wn * WN + j * 16], BST);
#pragma unroll
            for (int i = 0; i < 2; i++)
#pragma unroll
                for (int j = 0; j < NFR; j++)
                    wmma::mma_sync(acc[i][j], af[i], bfr[j], acc[i][j]);
        }
        if (kt + 2 < NK) load_stage(kt + 2, (kt + 2) % 3);
        CP_COMMIT();
    }
    __syncthreads();

#pragma unroll
    for (int i = 0; i < 2; i++)
#pragma unroll
        for (int j = 0; j < NFR; j++)
            wmma::store_matrix_sync(&Cs[(wm * 32 + i * 16) * CST + wn * WN + j * 16],
                                    acc[i][j], CST, wmma::mem_row_major);
    __syncthreads();

    for (int e = tid; e < 128 * (NTL / 8); e += 256) {
        int r  = e / (NTL / 8);
        int c8 = (e % (NTL / 8)) * 8;
        int m  = m0 + r;
        int nb = n0 + c8;
        const float* crow = &Cs[r * CST + c8];
        size_t pos = (size_t)m * Cv + nb;
#pragma unroll
        for (int u = 0; u < 8; u += 4) {
            float4 v  = *(const float4*)&crow[u];
            float4 bv = *(const float4*)&bias[nb + u];
            float4 xv = *(const float4*)&g_x1[pos + u];
            float4 o = make_float4(v.x + bv.x + xv.x, v.y + bv.y + xv.y,
                                   v.z + bv.z + xv.z, v.w + bv.w + xv.w);
            *(float4*)&outf[pos + u] = o;
        }
    }
}

// ---------------- launch ----------------
extern "C" void kernel_launch(void* const* d_in, const int* in_sizes, int n_in,
                              void* d_out, int out_size) {
    const float* x      = (const float*)d_in[0];
    const float* ln1_g  = (const float*)d_in[1];
    const float* ln1_b  = (const float*)d_in[2];
    const float* qkv_w  = (const float*)d_in[3];
    const float* qkv_b  = (const float*)d_in[4];
    const float* proj_w = (const float*)d_in[5];
    const float* proj_b = (const float*)d_in[6];
    const float* rpb    = (const float*)d_in[7];
    const float* ln2_g  = (const float*)d_in[8];
    const float* ln2_b  = (const float*)d_in[9];
    const float* mlp_w1 = (const float*)d_in[10];
    const float* mlp_b1 = (const float*)d_in[11];
    const float* mlp_w2 = (const float*)d_in[12];
    const float* mlp_b2 = (const float*)d_in[13];
    float* out = (float*)d_out;

    constexpr size_t W96  = wk_smem(96);
    constexpr size_t W64  = wk_smem(64);
    constexpr size_t W128 = wk_smem(128);
    constexpr size_t S64  = gemm_smem(64);
    cudaFuncSetAttribute(gemm_wk<0, 96>,  cudaFuncAttributeMaxDynamicSharedMemorySize, (int)W96);
    cudaFuncSetAttribute(gemm_wk<1, 64>,  cudaFuncAttributeMaxDynamicSharedMemorySize, (int)W64);
    cudaFuncSetAttribute(gemm_wk<2, 128>, cudaFuncAttributeMaxDynamicSharedMemorySize, (int)W128);
    cudaFuncSetAttribute(gemm3_k<64>,     cudaFuncAttributeMaxDynamicSharedMemorySize, (int)S64);
    cudaFuncSetAttribute(attn_wmma,       cudaFuncAttributeMaxDynamicSharedMemorySize, ATTN_SMEM);

    cvt_weights<<<432, 1024>>>(qkv_w, proj_w, mlp_w1, mlp_w2);
    bm_kernel<<<(64 * HEADS * NT * 52 + 255) / 256, 256>>>(rpb);
    ln1_kernel<<<MT / 8, 256>>>(x, ln1_g, ln1_b);
    gemm_wk<0, 96><<<dim3(576 / 96, MT / 128), 256, W96>>>(qkv_b, nullptr);
    attn_wmma<<<Bv * 64, 256, ATTN_SMEM>>>();
    gemm_wk<1, 64><<<dim3(192 / 64, MT / 128), 256, W64>>>(proj_b, x);
    ln2_kernel<<<MT / 8, 256>>>(ln2_g, ln2_b);
    gemm_wk<2, 128><<<dim3(768 / 128, MT / 128), 256, W128>>>(mlp_b1, nullptr);
    gemm3_k<64><<<dim3(192 / 64, MT / 128), 256, S64>>>(mlp_b2, out);
}